// round 3
// baseline (speedup 1.0000x reference)
#include <cuda_runtime.h>

// LSTM seq2seq: B=16384, S=T=64, I=4, M=16, H=64
// 128 CTAs x 256 threads. Thread = 2 gate rows x half-K (k-split across warp halves).
// Activations broadcast via LDS.128; weights resident in registers; FFMA2 (f32x2).

#define SEQ 64
typedef unsigned long long ull;

__device__ __forceinline__ void fma2(ull& d, ull a, ull b) {
    asm("fma.rn.f32x2 %0, %1, %2, %0;" : "+l"(d) : "l"(a), "l"(b));
}
__device__ __forceinline__ ull addf2(ull a, ull b) {
    ull r; asm("add.rn.f32x2 %0, %1, %2;" : "=l"(r) : "l"(a), "l"(b)); return r;
}
__device__ __forceinline__ float2 unpk(ull v) {
    float2 r; asm("mov.b64 {%0,%1}, %2;" : "=f"(r.x), "=f"(r.y) : "l"(v)); return r;
}
__device__ __forceinline__ ull packf2(float x, float y) {
    ull r; asm("mov.b64 %0, {%1,%2};" : "=l"(r) : "f"(x), "f"(y)); return r;
}
__device__ __forceinline__ float fexp2a(float x) { float y; asm("ex2.approx.f32 %0, %1;" : "=f"(y) : "f"(x)); return y; }
__device__ __forceinline__ float frcpa (float x) { float y; asm("rcp.approx.f32 %0, %1;" : "=f"(y) : "f"(x)); return y; }
__device__ __forceinline__ float sig_f (float x) { return frcpa(1.0f + fexp2a(-1.4426950408889634f * x)); }
__device__ __forceinline__ float tanh_f(float x) { return 2.0f * frcpa(1.0f + fexp2a(-2.8853900817779268f * x)) - 1.0f; }

// smem float offsets
// ACT quad rows: [0..3]=MID(16), [4..19]=H1(64), [20..35]=H2(64); each quad row = 128 float4
#define OFF_ACT   0
#define OFF_C1    18432            // float4 [16][128] = 8192 floats
#define OFF_C2    26624
#define OFF_G     34816            // ull [2][128][33] = 16896 floats
#define OFF_X     51712            // float4 [128] = 512 floats
#define OFF_WOUT  52224            // 256
#define OFF_WIN   52480            // 64
#define OFF_BIN   52544            // 16
#define OFF_BOUT  52560            // 4
#define SMEM_FLOATS 52564

// Gate pass: this thread computes rows (rp, rp+128) partial sums over its k-half,
// for 32 batch columns. base points at this k-half's first activation quad.
template<int NQ>
__device__ __forceinline__ void gate_pass(
    const ulonglong2* __restrict__ base,
    const ull* __restrict__ wA, const ull* __restrict__ wB,
    ull bias0, ull bias1, ull* __restrict__ G2kh, int rp, int bbase)
{
#pragma unroll 1
    for (int b2 = 0; b2 < 32; ++b2) {
        const int b = bbase + b2;
        ull a00 = bias0, a01 = 0ull, a10 = bias1, a11 = 0ull;
#pragma unroll
        for (int q = 0; q < NQ; ++q) {
            ulonglong2 v = base[q * 128 + b];
            fma2(a00, wA[2*q],   v.x);
            fma2(a01, wA[2*q+1], v.y);
            fma2(a10, wB[2*q],   v.x);
            fma2(a11, wB[2*q+1], v.y);
        }
        float2 s0 = unpk(addf2(a00, a01));
        float2 s1 = unpk(addf2(a10, a11));
        G2kh[rp * 33 + b2] = packf2(s0.x + s0.y, s1.x + s1.y);
    }
}

// Combine: 512 (quad, b2) items over 256 threads -> 2 each.
// G2[u] holds (row u, row u+128) = (i_u, g_u); G2[u+64] = (f_u, o_u).
__device__ __forceinline__ void combine_pass(
    const ull* __restrict__ G2, float4* __restrict__ Cq, float4* __restrict__ Hq,
    int tid, int bbase)
{
#pragma unroll
    for (int it = 0; it < 2; ++it) {
        const int item = tid + it * 256;
        const int q  = item >> 5;
        const int b2 = item & 31;
        const int b  = bbase + b2;
        float4 c = Cq[q * 128 + b];
        float4 h;
        float* cp = &c.x; float* hp = &h.x;
#pragma unroll
        for (int j = 0; j < 4; ++j) {
            const int u = q * 4 + j;
            float2 ig = unpk(addf2(G2[u * 33 + b2],        G2[128*33 + u * 33 + b2]));
            float2 fo = unpk(addf2(G2[(u + 64) * 33 + b2], G2[128*33 + (u + 64) * 33 + b2]));
            float cc = sig_f(fo.x) * cp[j] + sig_f(ig.x) * tanh_f(ig.y);
            cp[j] = cc;
            hp[j] = sig_f(fo.y) * tanh_f(cc);
        }
        Cq[q * 128 + b] = c;
        Hq[q * 128 + b] = h;
    }
}

// Load this thread's weight registers for one (enc|dec) phase.
__device__ __forceinline__ void load_weights(
    const float* Wih0, const float* Whh0, const float* b0v,
    const float* Wih1, const float* Whh1, const float* b1v,
    int rp, int kh,
    ull* wA0, ull* wA1, ull* wB0, ull* wB1,
    ull& bpA0, ull& bpA1, ull& bpB0, ull& bpB1)
{
    const int r0 = rp, r1 = rp + 128;
    const ull* xi0 = (const ull*)Wih0;   // [256][8]
    const ull* hh0 = (const ull*)Whh0;   // [256][32]
#pragma unroll
    for (int p = 0; p < 20; ++p) {
        const int kp = kh * 20 + p;
        wA0[p] = (kp < 8) ? xi0[r0 * 8 + kp] : hh0[r0 * 32 + (kp - 8)];
        wA1[p] = (kp < 8) ? xi0[r1 * 8 + kp] : hh0[r1 * 32 + (kp - 8)];
    }
    const ull* c1 = kh ? (const ull*)Whh1 : (const ull*)Wih1;  // [256][32]
#pragma unroll
    for (int p = 0; p < 32; ++p) { wB0[p] = c1[r0 * 32 + p]; wB1[p] = c1[r1 * 32 + p]; }
    if (kh == 0) {
        bpA0 = packf2(b0v[r0], 0.f); bpA1 = packf2(b0v[r1], 0.f);
        bpB0 = packf2(b1v[r0], 0.f); bpB1 = packf2(b1v[r1], 0.f);
    } else {
        bpA0 = 0ull; bpA1 = 0ull; bpB0 = 0ull; bpB1 = 0ull;
    }
}

// mid = W_in @ x + b_in, one batch column (b = tid < 128), quad layout rows 0..3
__device__ __forceinline__ void mid_store(float4 x, int b, float* sm)
{
    const float* WIN = sm + OFF_WIN;
    const float* BIN = sm + OFF_BIN;
    float4* MQ = (float4*)(sm + OFF_ACT);
#pragma unroll
    for (int g = 0; g < 4; ++g) {
        float4 v;
        float* vp = &v.x;
#pragma unroll
        for (int j = 0; j < 4; ++j) {
            const int m = g * 4 + j;
            vp[j] = BIN[m] + WIN[m*4]*x.x + WIN[m*4+1]*x.y + WIN[m*4+2]*x.z + WIN[m*4+3]*x.w;
        }
        MQ[g * 128 + b] = v;
    }
}

// One full timestep through both cells, 4 phases of 32 batch cols each.
__device__ __forceinline__ void run_step(
    const ull* wA0, const ull* wA1, const ull* wB0, const ull* wB1,
    ull bpA0, ull bpA1, ull bpB0, ull bpB1,
    float* sm, int tid, int rp, int kh)
{
    ulonglong2* ACTq = (ulonglong2*)(sm + OFF_ACT);
    const ulonglong2* base0 = ACTq + kh * 10 * 128;        // cell0: quads [0..19]
    const ulonglong2* base1 = ACTq + (4 + kh * 16) * 128;  // cell1: quads [4..35]
    ull* G2   = (ull*)(sm + OFF_G);
    ull* G2kh = G2 + kh * 128 * 33;
    float4* C1q = (float4*)(sm + OFF_C1);
    float4* C2q = (float4*)(sm + OFF_C2);
    float4* H1q = (float4*)(sm + OFF_ACT) + 4 * 128;
    float4* H2q = (float4*)(sm + OFF_ACT) + 20 * 128;

#pragma unroll 1
    for (int hb = 0; hb < 4; ++hb) {
        gate_pass<10>(base0, wA0, wA1, bpA0, bpA1, G2kh, rp, hb * 32);
        __syncthreads();
        combine_pass(G2, C1q, H1q, tid, hb * 32);
        __syncthreads();
    }
#pragma unroll 1
    for (int hb = 0; hb < 4; ++hb) {
        gate_pass<16>(base1, wB0, wB1, bpB0, bpB1, G2kh, rp, hb * 32);
        __syncthreads();
        combine_pass(G2, C2q, H2q, tid, hb * 32);
        __syncthreads();
    }
}

__global__ void __launch_bounds__(256, 1)
lstm_seq2seq_kernel(
    const float4* __restrict__ src4,   const float4* __restrict__ trg4,
    const float*  __restrict__ W_in,   const float*  __restrict__ b_in,
    const float*  __restrict__ eWih0,  const float*  __restrict__ eWhh0, const float* __restrict__ eb0,
    const float*  __restrict__ eWih1,  const float*  __restrict__ eWhh1, const float* __restrict__ eb1,
    const float*  __restrict__ dWih0,  const float*  __restrict__ dWhh0, const float* __restrict__ db0,
    const float*  __restrict__ dWih1,  const float*  __restrict__ dWhh1, const float* __restrict__ db1,
    const float*  __restrict__ W_out,  const float*  __restrict__ b_out,
    float4*       __restrict__ out4)
{
    extern __shared__ float sm[];
    const int tid  = threadIdx.x;
    const int wid  = tid >> 5;
    const int lane = tid & 31;
    const int kh   = wid >> 2;                 // k-half: warps 0-3 = 0, 4-7 = 1
    const int rp   = (wid & 3) * 32 + lane;    // row-pair index 0..127 -> rows rp, rp+128

    // consts
    if (tid < 64)  sm[OFF_WIN  + tid] = W_in[tid];
    if (tid < 256) sm[OFF_WOUT + tid] = W_out[tid];
    if (tid < 16)  sm[OFF_BIN  + tid] = b_in[tid];
    if (tid < 4)   sm[OFF_BOUT + tid] = b_out[tid];
    // zero H1,H2 (ACT quads 4..35) and C1,C2
    for (int i = tid; i < 16384; i += 256) sm[OFF_ACT + 2048 + i] = 0.f;
    for (int i = tid; i < 16384; i += 256) sm[OFF_C1 + i] = 0.f;
    __syncthreads();

    ull wA0[20], wA1[20], wB0[32], wB1[32];
    ull bpA0, bpA1, bpB0, bpB1;
    load_weights(eWih0, eWhh0, eb0, eWih1, eWhh1, eb1, rp, kh,
                 wA0, wA1, wB0, wB1, bpA0, bpA1, bpB0, bpB1);

    const size_t bg = (size_t)blockIdx.x * 128 + (tid & 127);

    // ================= ENCODER =================
    float4 xcur, xnext;
    if (tid < 128) xcur = __ldg(src4 + bg * SEQ);
    for (int t = 0; t < SEQ; ++t) {
        if (tid < 128) {
            mid_store(xcur, tid, sm);
            if (t + 1 < SEQ) xnext = __ldg(src4 + bg * SEQ + t + 1);
        }
        __syncthreads();
        run_step(wA0, wA1, wB0, wB1, bpA0, bpA1, bpB0, bpB1, sm, tid, rp, kh);
        xcur = xnext;
    }

    // reload decoder weights
    load_weights(dWih0, dWhh0, db0, dWih1, dWhh1, db1, rp, kh,
                 wA0, wA1, wB0, wB1, bpA0, bpA1, bpB0, bpB1);

    float4* Xs = (float4*)(sm + OFF_X);
    if (tid < 128) Xs[tid] = __ldg(trg4 + bg * SEQ);   // x0 = trg[:,0]
    __syncthreads();

    // ================= DECODER =================
    for (int t = 0; t < SEQ; ++t) {
        float4 tg;
        if (tid < 128) {
            mid_store(Xs[tid], tid, sm);
            tg = __ldg(trg4 + bg * SEQ + t);
        }
        __syncthreads();
        run_step(wA0, wA1, wB0, wB1, bpA0, bpA1, bpB0, bpB1, sm, tid, rp, kh);
        if (tid < 128) {
            // pred = W_out @ h2 + b_out
            const float* WOUT = sm + OFF_WOUT;
            const float4* H2q = (const float4*)(sm + OFF_ACT) + 20 * 128;
            float p0 = sm[OFF_BOUT+0], p1 = sm[OFF_BOUT+1], p2 = sm[OFF_BOUT+2], p3 = sm[OFF_BOUT+3];
#pragma unroll
            for (int q = 0; q < 16; ++q) {
                float4 h = H2q[q * 128 + tid];
                p0 += WOUT[0*64+q*4]*h.x + WOUT[0*64+q*4+1]*h.y + WOUT[0*64+q*4+2]*h.z + WOUT[0*64+q*4+3]*h.w;
                p1 += WOUT[1*64+q*4]*h.x + WOUT[1*64+q*4+1]*h.y + WOUT[1*64+q*4+2]*h.z + WOUT[1*64+q*4+3]*h.w;
                p2 += WOUT[2*64+q*4]*h.x + WOUT[2*64+q*4+1]*h.y + WOUT[2*64+q*4+2]*h.z + WOUT[2*64+q*4+3]*h.w;
                p3 += WOUT[3*64+q*4]*h.x + WOUT[3*64+q*4+1]*h.y + WOUT[3*64+q*4+2]*h.z + WOUT[3*64+q*4+3]*h.w;
            }
            float4 xo;
            xo.x = p0 + tg.x; xo.y = p1 + tg.y; xo.z = p2 + tg.z; xo.w = p3 + tg.w;
            out4[bg * SEQ + t] = xo;
            Xs[tid] = xo;
        }
        __syncthreads();
    }
}

extern "C" void kernel_launch(void* const* d_in, const int* in_sizes, int n_in,
                              void* d_out, int out_size)
{
    (void)in_sizes; (void)n_in; (void)out_size;
    const float4* src   = (const float4*)d_in[0];
    const float4* trg   = (const float4*)d_in[1];
    const float*  W_in  = (const float*)d_in[2];
    const float*  b_in  = (const float*)d_in[3];
    const float*  eWih0 = (const float*)d_in[4];
    const float*  eWhh0 = (const float*)d_in[5];
    const float*  eb0   = (const float*)d_in[6];
    const float*  eWih1 = (const float*)d_in[7];
    const float*  eWhh1 = (const float*)d_in[8];
    const float*  eb1   = (const float*)d_in[9];
    const float*  dWih0 = (const float*)d_in[10];
    const float*  dWhh0 = (const float*)d_in[11];
    const float*  db0   = (const float*)d_in[12];
    const float*  dWih1 = (const float*)d_in[13];
    const float*  dWhh1 = (const float*)d_in[14];
    const float*  db1   = (const float*)d_in[15];
    const float*  W_out = (const float*)d_in[16];
    const float*  b_out = (const float*)d_in[17];
    float4* out = (float4*)d_out;

    const size_t smem_bytes = (size_t)SMEM_FLOATS * sizeof(float); // 210,256 B
    cudaFuncSetAttribute(lstm_seq2seq_kernel,
                         cudaFuncAttributeMaxDynamicSharedMemorySize, (int)smem_bytes);

    lstm_seq2seq_kernel<<<128, 256, smem_bytes>>>(
        src, trg, W_in, b_in,
        eWih0, eWhh0, eb0, eWih1, eWhh1, eb1,
        dWih0, dWhh0, db0, dWih1, dWhh1, db1,
        W_out, b_out, out);
}

// round 4
// speedup vs baseline: 1.0007x; 1.0007x over previous
#include <cuda_runtime.h>

// LSTM seq2seq: B=16384, S=T=64, I=4, M=16, H=64
// 128 CTAs x 256 threads. Thread = 2 gate rows x half-K (k-split across warp halves).
// Activations broadcast via LDS.128; weights resident in registers; FFMA2 (f32x2).

#define SEQ 64
typedef unsigned long long ull;

__device__ __forceinline__ void fma2(ull& d, ull a, ull b) {
    asm("fma.rn.f32x2 %0, %1, %2, %0;" : "+l"(d) : "l"(a), "l"(b));
}
__device__ __forceinline__ ull addf2(ull a, ull b) {
    ull r; asm("add.rn.f32x2 %0, %1, %2;" : "=l"(r) : "l"(a), "l"(b)); return r;
}
__device__ __forceinline__ float2 unpk(ull v) {
    float2 r; asm("mov.b64 {%0,%1}, %2;" : "=f"(r.x), "=f"(r.y) : "l"(v)); return r;
}
__device__ __forceinline__ ull packf2(float x, float y) {
    ull r; asm("mov.b64 %0, {%1,%2};" : "=l"(r) : "f"(x), "f"(y)); return r;
}
__device__ __forceinline__ float fexp2a(float x) { float y; asm("ex2.approx.f32 %0, %1;" : "=f"(y) : "f"(x)); return y; }
__device__ __forceinline__ float frcpa (float x) { float y; asm("rcp.approx.f32 %0, %1;" : "=f"(y) : "f"(x)); return y; }
__device__ __forceinline__ float sig_f (float x) { return frcpa(1.0f + fexp2a(-1.4426950408889634f * x)); }
__device__ __forceinline__ float tanh_f(float x) { return 2.0f * frcpa(1.0f + fexp2a(-2.8853900817779268f * x)) - 1.0f; }

// smem float offsets
// ACT quad rows: [0..3]=MID(16), [4..19]=H1(64), [20..35]=H2(64); each quad row = 128 float4
#define OFF_ACT   0
#define OFF_C1    18432            // float4 [16][128] = 8192 floats
#define OFF_C2    26624
#define OFF_G     34816            // ull [2][128][33] = 16896 floats
#define OFF_X     51712            // float4 [128] = 512 floats
#define OFF_WOUT  52224            // 256
#define OFF_WIN   52480            // 64
#define OFF_BIN   52544            // 16
#define OFF_BOUT  52560            // 4
#define SMEM_FLOATS 52564

// Gate pass: this thread computes rows (rp, rp+128) partial sums over its k-half,
// for 32 batch columns. base points at this k-half's first activation quad.
template<int NQ>
__device__ __forceinline__ void gate_pass(
    const ulonglong2* __restrict__ base,
    const ull* __restrict__ wA, const ull* __restrict__ wB,
    ull bias0, ull bias1, ull* __restrict__ G2kh, int rp, int bbase)
{
#pragma unroll 1
    for (int b2 = 0; b2 < 32; ++b2) {
        const int b = bbase + b2;
        ull a00 = bias0, a01 = 0ull, a10 = bias1, a11 = 0ull;
#pragma unroll
        for (int q = 0; q < NQ; ++q) {
            ulonglong2 v = base[q * 128 + b];
            fma2(a00, wA[2*q],   v.x);
            fma2(a01, wA[2*q+1], v.y);
            fma2(a10, wB[2*q],   v.x);
            fma2(a11, wB[2*q+1], v.y);
        }
        float2 s0 = unpk(addf2(a00, a01));
        float2 s1 = unpk(addf2(a10, a11));
        G2kh[rp * 33 + b2] = packf2(s0.x + s0.y, s1.x + s1.y);
    }
}

// Combine: 512 (quad, b2) items over 256 threads -> 2 each.
// G2[u] holds (row u, row u+128) = (i_u, g_u); G2[u+64] = (f_u, o_u).
__device__ __forceinline__ void combine_pass(
    const ull* __restrict__ G2, float4* __restrict__ Cq, float4* __restrict__ Hq,
    int tid, int bbase)
{
#pragma unroll
    for (int it = 0; it < 2; ++it) {
        const int item = tid + it * 256;
        const int q  = item >> 5;
        const int b2 = item & 31;
        const int b  = bbase + b2;
        float4 c = Cq[q * 128 + b];
        float4 h;
        float* cp = &c.x; float* hp = &h.x;
#pragma unroll
        for (int j = 0; j < 4; ++j) {
            const int u = q * 4 + j;
            float2 ig = unpk(addf2(G2[u * 33 + b2],        G2[128*33 + u * 33 + b2]));
            float2 fo = unpk(addf2(G2[(u + 64) * 33 + b2], G2[128*33 + (u + 64) * 33 + b2]));
            float cc = sig_f(fo.x) * cp[j] + sig_f(ig.x) * tanh_f(ig.y);
            cp[j] = cc;
            hp[j] = sig_f(fo.y) * tanh_f(cc);
        }
        Cq[q * 128 + b] = c;
        Hq[q * 128 + b] = h;
    }
}

// Load this thread's weight registers for one (enc|dec) phase.
__device__ __forceinline__ void load_weights(
    const float* Wih0, const float* Whh0, const float* b0v,
    const float* Wih1, const float* Whh1, const float* b1v,
    int rp, int kh,
    ull* wA0, ull* wA1, ull* wB0, ull* wB1,
    ull& bpA0, ull& bpA1, ull& bpB0, ull& bpB1)
{
    const int r0 = rp, r1 = rp + 128;
    const ull* xi0 = (const ull*)Wih0;   // [256][8]
    const ull* hh0 = (const ull*)Whh0;   // [256][32]
#pragma unroll
    for (int p = 0; p < 20; ++p) {
        const int kp = kh * 20 + p;
        wA0[p] = (kp < 8) ? xi0[r0 * 8 + kp] : hh0[r0 * 32 + (kp - 8)];
        wA1[p] = (kp < 8) ? xi0[r1 * 8 + kp] : hh0[r1 * 32 + (kp - 8)];
    }
    const ull* c1 = kh ? (const ull*)Whh1 : (const ull*)Wih1;  // [256][32]
#pragma unroll
    for (int p = 0; p < 32; ++p) { wB0[p] = c1[r0 * 32 + p]; wB1[p] = c1[r1 * 32 + p]; }
    if (kh == 0) {
        bpA0 = packf2(b0v[r0], 0.f); bpA1 = packf2(b0v[r1], 0.f);
        bpB0 = packf2(b1v[r0], 0.f); bpB1 = packf2(b1v[r1], 0.f);
    } else {
        bpA0 = 0ull; bpA1 = 0ull; bpB0 = 0ull; bpB1 = 0ull;
    }
}

// mid = W_in @ x + b_in, one batch column (b = tid < 128), quad layout rows 0..3
__device__ __forceinline__ void mid_store(float4 x, int b, float* sm)
{
    const float* WIN = sm + OFF_WIN;
    const float* BIN = sm + OFF_BIN;
    float4* MQ = (float4*)(sm + OFF_ACT);
#pragma unroll
    for (int g = 0; g < 4; ++g) {
        float4 v;
        float* vp = &v.x;
#pragma unroll
        for (int j = 0; j < 4; ++j) {
            const int m = g * 4 + j;
            vp[j] = BIN[m] + WIN[m*4]*x.x + WIN[m*4+1]*x.y + WIN[m*4+2]*x.z + WIN[m*4+3]*x.w;
        }
        MQ[g * 128 + b] = v;
    }
}

// One full timestep through both cells, 4 phases of 32 batch cols each.
__device__ __forceinline__ void run_step(
    const ull* wA0, const ull* wA1, const ull* wB0, const ull* wB1,
    ull bpA0, ull bpA1, ull bpB0, ull bpB1,
    float* sm, int tid, int rp, int kh)
{
    ulonglong2* ACTq = (ulonglong2*)(sm + OFF_ACT);
    const ulonglong2* base0 = ACTq + kh * 10 * 128;        // cell0: quads [0..19]
    const ulonglong2* base1 = ACTq + (4 + kh * 16) * 128;  // cell1: quads [4..35]
    ull* G2   = (ull*)(sm + OFF_G);
    ull* G2kh = G2 + kh * 128 * 33;
    float4* C1q = (float4*)(sm + OFF_C1);
    float4* C2q = (float4*)(sm + OFF_C2);
    float4* H1q = (float4*)(sm + OFF_ACT) + 4 * 128;
    float4* H2q = (float4*)(sm + OFF_ACT) + 20 * 128;

#pragma unroll 1
    for (int hb = 0; hb < 4; ++hb) {
        gate_pass<10>(base0, wA0, wA1, bpA0, bpA1, G2kh, rp, hb * 32);
        __syncthreads();
        combine_pass(G2, C1q, H1q, tid, hb * 32);
        __syncthreads();
    }
#pragma unroll 1
    for (int hb = 0; hb < 4; ++hb) {
        gate_pass<16>(base1, wB0, wB1, bpB0, bpB1, G2kh, rp, hb * 32);
        __syncthreads();
        combine_pass(G2, C2q, H2q, tid, hb * 32);
        __syncthreads();
    }
}

__global__ void __launch_bounds__(256, 1)
lstm_seq2seq_kernel(
    const float4* __restrict__ src4,   const float4* __restrict__ trg4,
    const float*  __restrict__ W_in,   const float*  __restrict__ b_in,
    const float*  __restrict__ eWih0,  const float*  __restrict__ eWhh0, const float* __restrict__ eb0,
    const float*  __restrict__ eWih1,  const float*  __restrict__ eWhh1, const float* __restrict__ eb1,
    const float*  __restrict__ dWih0,  const float*  __restrict__ dWhh0, const float* __restrict__ db0,
    const float*  __restrict__ dWih1,  const float*  __restrict__ dWhh1, const float* __restrict__ db1,
    const float*  __restrict__ W_out,  const float*  __restrict__ b_out,
    float4*       __restrict__ out4)
{
    extern __shared__ float sm[];
    const int tid  = threadIdx.x;
    const int wid  = tid >> 5;
    const int lane = tid & 31;
    const int kh   = wid >> 2;                 // k-half: warps 0-3 = 0, 4-7 = 1
    const int rp   = (wid & 3) * 32 + lane;    // row-pair index 0..127 -> rows rp, rp+128

    // consts
    if (tid < 64)  sm[OFF_WIN  + tid] = W_in[tid];
    if (tid < 256) sm[OFF_WOUT + tid] = W_out[tid];
    if (tid < 16)  sm[OFF_BIN  + tid] = b_in[tid];
    if (tid < 4)   sm[OFF_BOUT + tid] = b_out[tid];
    // zero H1,H2 (ACT quads 4..35) and C1,C2
    for (int i = tid; i < 16384; i += 256) sm[OFF_ACT + 2048 + i] = 0.f;
    for (int i = tid; i < 16384; i += 256) sm[OFF_C1 + i] = 0.f;
    __syncthreads();

    ull wA0[20], wA1[20], wB0[32], wB1[32];
    ull bpA0, bpA1, bpB0, bpB1;
    load_weights(eWih0, eWhh0, eb0, eWih1, eWhh1, eb1, rp, kh,
                 wA0, wA1, wB0, wB1, bpA0, bpA1, bpB0, bpB1);

    const size_t bg = (size_t)blockIdx.x * 128 + (tid & 127);

    // ================= ENCODER =================
    float4 xcur, xnext;
    if (tid < 128) xcur = __ldg(src4 + bg * SEQ);
    for (int t = 0; t < SEQ; ++t) {
        if (tid < 128) {
            mid_store(xcur, tid, sm);
            if (t + 1 < SEQ) xnext = __ldg(src4 + bg * SEQ + t + 1);
        }
        __syncthreads();
        run_step(wA0, wA1, wB0, wB1, bpA0, bpA1, bpB0, bpB1, sm, tid, rp, kh);
        xcur = xnext;
    }

    // reload decoder weights
    load_weights(dWih0, dWhh0, db0, dWih1, dWhh1, db1, rp, kh,
                 wA0, wA1, wB0, wB1, bpA0, bpA1, bpB0, bpB1);

    float4* Xs = (float4*)(sm + OFF_X);
    if (tid < 128) Xs[tid] = __ldg(trg4 + bg * SEQ);   // x0 = trg[:,0]
    __syncthreads();

    // ================= DECODER =================
    for (int t = 0; t < SEQ; ++t) {
        float4 tg;
        if (tid < 128) {
            mid_store(Xs[tid], tid, sm);
            tg = __ldg(trg4 + bg * SEQ + t);
        }
        __syncthreads();
        run_step(wA0, wA1, wB0, wB1, bpA0, bpA1, bpB0, bpB1, sm, tid, rp, kh);
        if (tid < 128) {
            // pred = W_out @ h2 + b_out
            const float* WOUT = sm + OFF_WOUT;
            const float4* H2q = (const float4*)(sm + OFF_ACT) + 20 * 128;
            float p0 = sm[OFF_BOUT+0], p1 = sm[OFF_BOUT+1], p2 = sm[OFF_BOUT+2], p3 = sm[OFF_BOUT+3];
#pragma unroll
            for (int q = 0; q < 16; ++q) {
                float4 h = H2q[q * 128 + tid];
                p0 += WOUT[0*64+q*4]*h.x + WOUT[0*64+q*4+1]*h.y + WOUT[0*64+q*4+2]*h.z + WOUT[0*64+q*4+3]*h.w;
                p1 += WOUT[1*64+q*4]*h.x + WOUT[1*64+q*4+1]*h.y + WOUT[1*64+q*4+2]*h.z + WOUT[1*64+q*4+3]*h.w;
                p2 += WOUT[2*64+q*4]*h.x + WOUT[2*64+q*4+1]*h.y + WOUT[2*64+q*4+2]*h.z + WOUT[2*64+q*4+3]*h.w;
                p3 += WOUT[3*64+q*4]*h.x + WOUT[3*64+q*4+1]*h.y + WOUT[3*64+q*4+2]*h.z + WOUT[3*64+q*4+3]*h.w;
            }
            float4 xo;
            xo.x = p0 + tg.x; xo.y = p1 + tg.y; xo.z = p2 + tg.z; xo.w = p3 + tg.w;
            out4[bg * SEQ + t] = xo;
            Xs[tid] = xo;
        }
        __syncthreads();
    }
}

extern "C" void kernel_launch(void* const* d_in, const int* in_sizes, int n_in,
                              void* d_out, int out_size)
{
    (void)in_sizes; (void)n_in; (void)out_size;
    const float4* src   = (const float4*)d_in[0];
    const float4* trg   = (const float4*)d_in[1];
    const float*  W_in  = (const float*)d_in[2];
    const float*  b_in  = (const float*)d_in[3];
    const float*  eWih0 = (const float*)d_in[4];
    const float*  eWhh0 = (const float*)d_in[5];
    const float*  eb0   = (const float*)d_in[6];
    const float*  eWih1 = (const float*)d_in[7];
    const float*  eWhh1 = (const float*)d_in[8];
    const float*  eb1   = (const float*)d_in[9];
    const float*  dWih0 = (const float*)d_in[10];
    const float*  dWhh0 = (const float*)d_in[11];
    const float*  db0   = (const float*)d_in[12];
    const float*  dWih1 = (const float*)d_in[13];
    const float*  dWhh1 = (const float*)d_in[14];
    const float*  db1   = (const float*)d_in[15];
    const float*  W_out = (const float*)d_in[16];
    const float*  b_out = (const float*)d_in[17];
    float4* out = (float4*)d_out;

    const size_t smem_bytes = (size_t)SMEM_FLOATS * sizeof(float); // 210,256 B
    cudaFuncSetAttribute(lstm_seq2seq_kernel,
                         cudaFuncAttributeMaxDynamicSharedMemorySize, (int)smem_bytes);

    lstm_seq2seq_kernel<<<128, 256, smem_bytes>>>(
        src, trg, W_in, b_in,
        eWih0, eWhh0, eb0, eWih1, eWhh1, eb1,
        dWih0, dWhh0, db0, dWih1, dWhh1, db1,
        W_out, b_out, out);
}